// round 12
// baseline (speedup 1.0000x reference)
#include <cuda_runtime.h>
#include <cstdint>

#define T_LEN 4096
#define IN_DIM 256
#define H_DIM 1024
#define G4H   4096
#define NCTA  128
#define UNITS 8     // hidden units per CTA (128 * 8 = 1024); warp w computes unit w
#define NREP  8     // publish-buffer replicas (slice de-amplification)

// ---------------- device scratch (static: no allocations allowed) ----------
__device__ float g_xz[(size_t)T_LEN * G4H];     // 64 MB: input projections
__device__ float g_hall[(size_t)T_LEN * H_DIM]; // 16 MB: h outputs of current layer
// Fused data+flag publish buffers, replicated NREP x to spread L2-slice load:
// entry = {tag : hi32, h_bits : lo32}, single 8B relaxed store per entry.
// Tag = layer*(T_LEN+1) + t + 1 for step t; layer*(T_LEN+1) for h_{-1}.
// Equality-checked; replay-safe (stale tags from other layers/replays never
// equal the expected tag; zero-init == layer-0 h_{-1} with value 0).
// 128-byte aligned so 16B vector polls are legal at 32B/thread offsets.
__device__ __align__(128) unsigned long long g_pub[2][NREP][H_DIM];

// ---------------- memory-order helpers --------------------------------------
__device__ __forceinline__ void st_relaxed64(unsigned long long* p, unsigned long long v) {
    asm volatile("st.relaxed.gpu.global.b64 [%0], %1;" :: "l"(p), "l"(v) : "memory");
}
// 16B volatile poll: two 8B elements, each naturally 8B-atomic (producers
// write each element with a single 8B store). Volatile => L2-fresh each time.
__device__ __forceinline__ void ld_vol_v2(const unsigned long long* p,
                                          unsigned long long& a,
                                          unsigned long long& b) {
    asm volatile("ld.volatile.global.v2.b64 {%0, %1}, [%2];"
                 : "=l"(a), "=l"(b) : "l"(p) : "memory");
}

// ---------------- packed f32x2 FMA helper ----------------------------------
union F2u { float2 f; unsigned long long u; };

__device__ __forceinline__ void fma2(unsigned long long& d,
                                     unsigned long long a,
                                     unsigned long long b) {
    asm volatile("fma.rn.f32x2 %0, %1, %2, %0;" : "+l"(d) : "l"(a), "l"(b));
}

// ---------------- fast, overflow-safe activations ---------------------------
__device__ __forceinline__ float fast_sigmoid(float x) {
    return __fdividef(1.f, 1.f + __expf(-x));
}
__device__ __forceinline__ float fast_tanh(float x) {
    float a = fabsf(x);
    float e = __expf(-2.f * a);               // in (0, 1], never overflows
    float t = (1.f - e) * __fdividef(1.f, 1.f + e);
    return copysignf(t, x);
}

// ---------------- GEMM: xz = A @ W^T + bias --------------------------------
template<int K>
__global__ __launch_bounds__(256, 2)
void gemm_xz(const float* __restrict__ A_in,
             const float* __restrict__ W,
             const float* __restrict__ bias) {
    const float* A = A_in ? A_in : g_hall;   // nullptr => previous layer's h

    __shared__ float As[16][132];
    __shared__ float Bs[16][132];

    const int tid  = threadIdx.x;
    const int row0 = blockIdx.y * 128;
    const int col0 = blockIdx.x * 128;
    const int ty   = tid >> 4;
    const int tx   = tid & 15;

    float acc[8][8];
#pragma unroll
    for (int i = 0; i < 8; i++)
#pragma unroll
        for (int j = 0; j < 8; j++) acc[i][j] = 0.f;

    for (int k0 = 0; k0 < K; k0 += 16) {
#pragma unroll
        for (int i = 0; i < 2; i++) {
            int f  = tid + i * 256;
            int r  = f >> 2;
            int c4 = f & 3;
            float4 va = *(const float4*)(A + (size_t)(row0 + r) * K + k0 + c4 * 4);
            As[c4 * 4 + 0][r] = va.x;
            As[c4 * 4 + 1][r] = va.y;
            As[c4 * 4 + 2][r] = va.z;
            As[c4 * 4 + 3][r] = va.w;
            float4 vb = *(const float4*)(W + (size_t)(col0 + r) * K + k0 + c4 * 4);
            Bs[c4 * 4 + 0][r] = vb.x;
            Bs[c4 * 4 + 1][r] = vb.y;
            Bs[c4 * 4 + 2][r] = vb.z;
            Bs[c4 * 4 + 3][r] = vb.w;
        }
        __syncthreads();

#pragma unroll
        for (int k = 0; k < 16; k++) {
            float4 a0 = *(const float4*)&As[k][ty * 8];
            float4 a1 = *(const float4*)&As[k][ty * 8 + 4];
            float4 b0 = *(const float4*)&Bs[k][tx * 8];
            float4 b1 = *(const float4*)&Bs[k][tx * 8 + 4];
            float a[8] = {a0.x, a0.y, a0.z, a0.w, a1.x, a1.y, a1.z, a1.w};
            float b[8] = {b0.x, b0.y, b0.z, b0.w, b1.x, b1.y, b1.z, b1.w};
#pragma unroll
            for (int i = 0; i < 8; i++)
#pragma unroll
                for (int j = 0; j < 8; j++) acc[i][j] += a[i] * b[j];
        }
        __syncthreads();
    }

    float bj[8];
#pragma unroll
    for (int j = 0; j < 8; j++) bj[j] = bias[col0 + tx * 8 + j];

#pragma unroll
    for (int i = 0; i < 8; i++) {
        int r = row0 + ty * 8 + i;
#pragma unroll
        for (int j = 0; j < 8; j++) {
            g_xz[(size_t)r * G4H + col0 + tx * 8 + j] = acc[i][j] + bj[j];
        }
    }
}

// ---------------- recurrent scan -------------------------------------------
// 128 CTAs x 256 threads, all co-resident. CTA b owns hidden units [8b, 8b+8).
// Warp w owns ALL 4 GATES of unit 8b+w; lane 0 computes the gates -> 8 units'
// gate chains run in PARALLEL across warps.
// Publish: split-barrier. Warps 1..7 post packed {tag,h} to smem and
// bar.arrive(1) -> run ahead to next step's poll. Warp 0 bar.sync(1), then
// publishes ALL 8 units x 8 replicas in TWO coalesced store waves.
// Poll: per-thread own 32B of replica (bid&7) via 2x16B volatile vector
// loads, software-pipelined, NO backoff (tail quantization hurts the 128-way
// max). sh_h double-buffered by parity.
__global__ __launch_bounds__(256, 1)
void lstm_scan(const float* __restrict__ Whh, int layer) {
    __shared__ float sh_h[2][H_DIM];              // double-buffered h stage
    __shared__ unsigned long long sh_pk[UNITS];   // packed {tag,h} per unit

    const int bid   = blockIdx.x;
    const int tid   = threadIdx.x;
    const int wid   = tid >> 5;        // warp w -> unit ubase + w
    const int lane  = tid & 31;
    const int ubase = bid * UNITS;
    const int rep   = bid & (NREP - 1);
    const int unit  = ubase + wid;

    // W_hh rows for this warp: gate g of unit `unit`; lane covers cols
    // c*128 + lane*4 .. +3 for c = 0..7. 128 floats/thread in registers.
    float4 wreg[4][8];
#pragma unroll
    for (int g = 0; g < 4; g++) {
        const float4* wr =
            (const float4*)(Whh + ((size_t)g * H_DIM + unit) * H_DIM);
#pragma unroll
        for (int c = 0; c < 8; c++) wreg[g][c] = wr[c * 32 + lane];
    }

    const unsigned tagbase = (unsigned)layer * (unsigned)(T_LEN + 1);
    float c_state = 0.f;   // lane 0 of each warp carries its unit's cell state

    // publish h_{-1} = 0 with tag = tagbase into the parity-1 buffers:
    // warp 0, lane = r*8+u covers replicas 0..3; second wave replicas 4..7.
    if (wid == 0) {
        const int r = lane >> 3, u = lane & 7;
        unsigned long long pk0 = (unsigned long long)tagbase << 32;
        st_relaxed64(&g_pub[1][r][ubase + u], pk0);
        st_relaxed64(&g_pub[1][r + 4][ubase + u], pk0);
    }

    for (int t = 0; t < T_LEN; t++) {
        // prefetch xz for this warp's unit (lane 0; independent of h)
        float xzi = 0.f, xzf = 0.f, xzg = 0.f, xzo = 0.f;
        if (lane == 0) {
            const float* xz = g_xz + (size_t)t * G4H + unit;
            xzi = __ldg(xz);
            xzf = __ldg(xz + H_DIM);
            xzg = __ldg(xz + 2 * H_DIM);
            xzo = __ldg(xz + 3 * H_DIM);
        }

        const int par = (t + 1) & 1;                      // parity of h_{t-1}
        const unsigned exp_tag = tagbase + (unsigned)t;   // tag of h_{t-1}

        // wait for h_{t-1}: thread tid owns 4 fused slots (32B) of OUR replica;
        // 2 x 16B volatile loads, software-pipelined, tight spin (no sleep).
        {
            const unsigned long long* buf = &g_pub[par][rep][4 * tid];
            unsigned long long a0, a1, a2, a3;
            ld_vol_v2(buf + 0, a0, a1);
            ld_vol_v2(buf + 2, a2, a3);
            for (;;) {
                unsigned long long b0, b1, b2, b3;
                ld_vol_v2(buf + 0, b0, b1);       // next batch in flight
                ld_vol_v2(buf + 2, b2, b3);
                bool ok = ((unsigned)(a0 >> 32) == exp_tag) &
                          ((unsigned)(a1 >> 32) == exp_tag) &
                          ((unsigned)(a2 >> 32) == exp_tag) &
                          ((unsigned)(a3 >> 32) == exp_tag);
                if (ok) break;
                a0 = b0; a1 = b1; a2 = b2; a3 = b3;
            }
            ((float4*)sh_h[par])[tid] =
                make_float4(__uint_as_float((unsigned)a0),
                            __uint_as_float((unsigned)a1),
                            __uint_as_float((unsigned)a2),
                            __uint_as_float((unsigned)a3));
        }
        __syncthreads();                                   // (B) -- only full bar

        // packed dot products: 4 gate-rows of our unit, 32 cols per lane
        unsigned long long acc[4];
        {
            F2u z; z.f = make_float2(0.f, 0.f);
            acc[0] = acc[1] = acc[2] = acc[3] = z.u;
        }
        const float4* hbuf = (const float4*)sh_h[par];
#pragma unroll
        for (int c = 0; c < 8; c++) {
            float4 hv = hbuf[c * 32 + lane];
            F2u hlo, hhi;
            hlo.f = make_float2(hv.x, hv.y);
            hhi.f = make_float2(hv.z, hv.w);
#pragma unroll
            for (int g = 0; g < 4; g++) {
                F2u wlo, whi;
                wlo.f = make_float2(wreg[g][c].x, wreg[g][c].y);
                whi.f = make_float2(wreg[g][c].z, wreg[g][c].w);
                fma2(acc[g], wlo.u, hlo.u);
                fma2(acc[g], whi.u, hhi.u);
            }
        }

        // 4 independent butterfly reductions, interleaved to pipeline
        float s0, s1, s2, s3;
        {
            F2u a0, a1, a2, a3;
            a0.u = acc[0]; a1.u = acc[1]; a2.u = acc[2]; a3.u = acc[3];
            s0 = a0.f.x + a0.f.y;
            s1 = a1.f.x + a1.f.y;
            s2 = a2.f.x + a2.f.y;
            s3 = a3.f.x + a3.f.y;
#pragma unroll
            for (int off = 16; off; off >>= 1) {
                s0 += __shfl_xor_sync(0xffffffffu, s0, off);
                s1 += __shfl_xor_sync(0xffffffffu, s1, off);
                s2 += __shfl_xor_sync(0xffffffffu, s2, off);
                s3 += __shfl_xor_sync(0xffffffffu, s3, off);
            }
        }

        // gates in parallel on lane 0 of EACH warp; post packed result to smem
        if (lane == 0) {
            float zi = s0 + xzi;
            float zf = s1 + xzf;
            float zg = s2 + xzg;
            float zo = s3 + xzo;
            float ig = fast_sigmoid(zi);
            float fg = fast_sigmoid(zf);
            float gg = fast_tanh(zg);
            float og = fast_sigmoid(zo);
            c_state  = fg * c_state + ig * gg;
            float h  = og * fast_tanh(c_state);
            sh_pk[wid] =
                ((unsigned long long)(exp_tag + 1u) << 32) |
                (unsigned long long)__float_as_uint(h);
            __stcg(&g_hall[(size_t)t * H_DIM + unit], h);  // consumed next launch
        }

        // split barrier: warps 1..7 arrive and RUN AHEAD to next step's poll;
        // warp 0 syncs (sees all sh_pk posts) and publishes everything.
        if (wid == 0) {
            asm volatile("bar.sync 1, 256;" ::: "memory");
            const int r = lane >> 3, u = lane & 7;          // lane = r*8 + u
            unsigned long long pk = sh_pk[u];
            st_relaxed64(&g_pub[t & 1][r][ubase + u], pk);     // replicas 0..3
            st_relaxed64(&g_pub[t & 1][r + 4][ubase + u], pk); // replicas 4..7
        } else {
            asm volatile("bar.arrive 1, 256;" ::: "memory");
        }
        // hazards: sh_pk writes@t precede arrive/sync@t (bar orders smem);
        // sh_pk writes@t+1 happen after (B)@t+1, which warp 0 reaches only
        // after its publish reads@t -> no overwrite race. sh_h[par] reuse at
        // t+2 is ordered against dot reads@t through (B)@t+1 (every thread's
        // stage@t+2 is after it passed (B)@t+1; every dot read@t is before
        // that thread arrived at (B)@t+1).
    }
}

// ---------------- final FC: out[t][o] = hall[t] . fcW[o] + fcb[o] ----------
__global__ void fc_kernel(const float* __restrict__ W,
                          const float* __restrict__ b,
                          float* __restrict__ out) {
    int t    = blockIdx.x;
    int o    = threadIdx.x >> 5;   // 10 warps
    int lane = threadIdx.x & 31;
    const float4* h = (const float4*)(g_hall + (size_t)t * H_DIM);
    const float4* w = (const float4*)(W + (size_t)o * H_DIM);
    float s = 0.f;
#pragma unroll
    for (int c = 0; c < 8; c++) {
        float4 hv = h[c * 32 + lane];
        float4 wv = w[c * 32 + lane];
        s += hv.x * wv.x + hv.y * wv.y + hv.z * wv.z + hv.w * wv.w;
    }
#pragma unroll
    for (int off = 16; off; off >>= 1)
        s += __shfl_xor_sync(0xffffffffu, s, off);
    if (lane == 0) out[t * 10 + o] = s + b[o];
}

// ---------------- launch ----------------------------------------------------
extern "C" void kernel_launch(void* const* d_in, const int* in_sizes, int n_in,
                              void* d_out, int out_size) {
    const float* x     = (const float*)d_in[0];
    const float* Wih0  = (const float*)d_in[1];
    const float* Whh0  = (const float*)d_in[2];
    const float* b0    = (const float*)d_in[3];
    const float* WihR  = (const float*)d_in[4];
    const float* WhhR  = (const float*)d_in[5];
    const float* bR    = (const float*)d_in[6];
    const float* fcW   = (const float*)d_in[7];
    const float* fcb   = (const float*)d_in[8];
    float*       out   = (float*)d_out;

    dim3 ggrid(G4H / 128, T_LEN / 128);
    dim3 gblk(256);

    // layer 0
    gemm_xz<IN_DIM><<<ggrid, gblk>>>(x, Wih0, b0);
    lstm_scan<<<NCTA, 256>>>(Whh0, 0);

    // layers 1..3
    for (int l = 1; l < 4; l++) {
        const float* Wih = WihR + (size_t)(l - 1) * G4H * H_DIM;
        const float* Whh = WhhR + (size_t)(l - 1) * G4H * H_DIM;
        const float* bb  = bR   + (size_t)(l - 1) * G4H;
        gemm_xz<H_DIM><<<ggrid, gblk>>>(nullptr /* = g_hall */, Wih, bb);
        lstm_scan<<<NCTA, 256>>>(Whh, l);
    }

    fc_kernel<<<T_LEN, 320>>>(fcW, fcb, out);
}

// round 13
// speedup vs baseline: 1.1394x; 1.1394x over previous
#include <cuda_runtime.h>
#include <cstdint>

#define T_LEN 4096
#define IN_DIM 256
#define H_DIM 1024
#define G4H   4096
#define NCTA  128
#define UNITS 8     // hidden units per CTA (128 * 8 = 1024)
#define NREP  4     // publish-buffer replicas (slice de-amplification)

// ---------------- device scratch (static: no allocations allowed) ----------
__device__ float g_xz[(size_t)T_LEN * G4H];     // 64 MB: input projections
__device__ float g_hall[(size_t)T_LEN * H_DIM]; // 16 MB: h outputs of current layer
// Fused data+flag publish buffers, replicated NREP x to spread L2-slice load:
// entry = {tag : hi32, h_bits : lo32}, single 8B relaxed store per entry.
// Tag = layer*(T_LEN+1) + t + 1 for step t; layer*(T_LEN+1) for h_{-1}.
// Equality-checked; replay-safe (stale tags from other layers/replays never
// equal the expected tag; zero-init == layer-0 h_{-1} with value 0).
__device__ unsigned long long g_pub[2][NREP][H_DIM];

// ---------------- memory-order helpers --------------------------------------
__device__ __forceinline__ unsigned long long ld_relaxed64(const unsigned long long* p) {
    unsigned long long v;
    asm volatile("ld.relaxed.gpu.global.b64 %0, [%1];" : "=l"(v) : "l"(p) : "memory");
    return v;
}
__device__ __forceinline__ void st_relaxed64(unsigned long long* p, unsigned long long v) {
    asm volatile("st.relaxed.gpu.global.b64 [%0], %1;" :: "l"(p), "l"(v) : "memory");
}

// ---------------- packed f32x2 FMA helpers ----------------------------------
union F2u { float2 f; unsigned long long u; };

__device__ __forceinline__ void fma2(unsigned long long& d,
                                     unsigned long long a,
                                     unsigned long long b) {
    asm volatile("fma.rn.f32x2 %0, %1, %2, %0;" : "+l"(d) : "l"(a), "l"(b));
}
__device__ __forceinline__ unsigned long long pack2(float lo, float hi) {
    unsigned long long r;
    asm("mov.b64 %0, {%1, %2};" : "=l"(r) : "f"(lo), "f"(hi));
    return r;
}

// ---------------- fast, overflow-safe activations ---------------------------
__device__ __forceinline__ float fast_sigmoid(float x) {
    return __fdividef(1.f, 1.f + __expf(-x));
}
__device__ __forceinline__ float fast_tanh(float x) {
    float a = fabsf(x);
    float e = __expf(-2.f * a);               // in (0, 1], never overflows
    float t = (1.f - e) * __fdividef(1.f, 1.f + e);
    return copysignf(t, x);
}

// ---------------- GEMM: xz = A @ W^T + bias --------------------------------
// 128x128 tile, 256 threads, 8x8 microtile, K-tile 16.
// Register-prefetch double buffering (next tile's global loads overlap the
// current tile's compute) + packed f32x2 accumulation (32 fma2 + 12 packs
// per k-iter instead of 64 FFMA).
template<int K>
__global__ __launch_bounds__(256)
void gemm_xz(const float* __restrict__ A_in,
             const float* __restrict__ W,
             const float* __restrict__ bias) {
    const float* A = A_in ? A_in : g_hall;   // nullptr => previous layer's h

    __shared__ float As[16][132];
    __shared__ float Bs[16][132];

    const int tid  = threadIdx.x;
    const int row0 = blockIdx.y * 128;
    const int col0 = blockIdx.x * 128;
    const int ty   = tid >> 4;     // 0..15
    const int tx   = tid & 15;     // 0..15
    const int lr   = tid >> 2;     // 0..63  (load row within half-tile)
    const int lc   = tid & 3;      // which float4 of the 16-wide k tile

    // packed accumulators: acc2[i][jj] = {out[2jj], out[2jj+1]} for row i
    unsigned long long acc2[8][4];
#pragma unroll
    for (int i = 0; i < 8; i++)
#pragma unroll
        for (int j = 0; j < 4; j++) acc2[i][j] = pack2(0.f, 0.f);

    const float* pA0 = A + (size_t)(row0 + lr) * K + lc * 4;
    const float* pA1 = A + (size_t)(row0 + lr + 64) * K + lc * 4;
    const float* pB0 = W + (size_t)(col0 + lr) * K + lc * 4;
    const float* pB1 = W + (size_t)(col0 + lr + 64) * K + lc * 4;

    // prologue: prefetch tile 0
    float4 fa0 = *(const float4*)(pA0);
    float4 fa1 = *(const float4*)(pA1);
    float4 fb0 = *(const float4*)(pB0);
    float4 fb1 = *(const float4*)(pB1);

    for (int k0 = 0; k0 < K; k0 += 16) {
        __syncthreads();   // previous compute done -> safe to overwrite smem
        As[lc * 4 + 0][lr] = fa0.x;
        As[lc * 4 + 1][lr] = fa0.y;
        As[lc * 4 + 2][lr] = fa0.z;
        As[lc * 4 + 3][lr] = fa0.w;
        As[lc * 4 + 0][lr + 64] = fa1.x;
        As[lc * 4 + 1][lr + 64] = fa1.y;
        As[lc * 4 + 2][lr + 64] = fa1.z;
        As[lc * 4 + 3][lr + 64] = fa1.w;
        Bs[lc * 4 + 0][lr] = fb0.x;
        Bs[lc * 4 + 1][lr] = fb0.y;
        Bs[lc * 4 + 2][lr] = fb0.z;
        Bs[lc * 4 + 3][lr] = fb0.w;
        Bs[lc * 4 + 0][lr + 64] = fb1.x;
        Bs[lc * 4 + 1][lr + 64] = fb1.y;
        Bs[lc * 4 + 2][lr + 64] = fb1.z;
        Bs[lc * 4 + 3][lr + 64] = fb1.w;
        __syncthreads();

        // prefetch NEXT tile into registers (overlaps the compute below)
        if (k0 + 16 < K) {
            fa0 = *(const float4*)(pA0 + k0 + 16);
            fa1 = *(const float4*)(pA1 + k0 + 16);
            fb0 = *(const float4*)(pB0 + k0 + 16);
            fb1 = *(const float4*)(pB1 + k0 + 16);
        }

#pragma unroll
        for (int k = 0; k < 16; k++) {
            float4 a0 = *(const float4*)&As[k][ty * 8];
            float4 a1 = *(const float4*)&As[k][ty * 8 + 4];
            float4 b0 = *(const float4*)&Bs[k][tx * 8];
            float4 b1 = *(const float4*)&Bs[k][tx * 8 + 4];
            unsigned long long bp[4];
            bp[0] = pack2(b0.x, b0.y);
            bp[1] = pack2(b0.z, b0.w);
            bp[2] = pack2(b1.x, b1.y);
            bp[3] = pack2(b1.z, b1.w);
            float a[8] = {a0.x, a0.y, a0.z, a0.w, a1.x, a1.y, a1.z, a1.w};
#pragma unroll
            for (int i = 0; i < 8; i++) {
                unsigned long long ap = pack2(a[i], a[i]);
#pragma unroll
                for (int j = 0; j < 4; j++) fma2(acc2[i][j], ap, bp[j]);
            }
        }
    }

    float bj[8];
#pragma unroll
    for (int j = 0; j < 8; j++) bj[j] = bias[col0 + tx * 8 + j];

#pragma unroll
    for (int i = 0; i < 8; i++) {
        int r = row0 + ty * 8 + i;
        float* orow = g_xz + (size_t)r * G4H + col0 + tx * 8;
#pragma unroll
        for (int j = 0; j < 4; j++) {
            F2u v; v.u = acc2[i][j];
            orow[2 * j + 0] = v.f.x + bj[2 * j + 0];
            orow[2 * j + 1] = v.f.y + bj[2 * j + 1];
        }
    }
}

// ---------------- recurrent scan (R8 verbatim -- proven 26.1 ms) ------------
// 128 CTAs x 256 threads, all co-resident. CTA b owns hidden units [8b, 8b+8).
// W_hh slice (32 rows x 1024) lives in REGISTERS (128 floats/thread).
// Sync fabric: fused {tag,h} 64-bit publish, replicated 4x.
//   producer lane u: NREP st.relaxed.b64
//   consumer: each thread spins INDEPENDENTLY on its own 4 slots (stops
//   loading once tagged), stages its h values to smem, then one barrier.
__global__ __launch_bounds__(256, 1)
void lstm_scan(const float* __restrict__ Whh, int layer) {
    __shared__ float sh_h[H_DIM];
    __shared__ float sh_z[32];

    const int bid   = blockIdx.x;
    const int tid   = threadIdx.x;
    const int wid   = tid >> 5;
    const int lane  = tid & 31;
    const int ubase = bid * UNITS;
    const int rep   = bid & (NREP - 1);

    // load this CTA's W_hh slice into registers.
    // warp w handles slice-rows s = 4w..4w+3, s -> (gate = s>>3, unit = s&7).
    float4 wreg[4][8];
#pragma unroll
    for (int j = 0; j < 4; j++) {
        int s    = wid * 4 + j;
        int gate = s >> 3;
        int unit = s & 7;
        const float4* wr =
            (const float4*)(Whh + ((size_t)gate * H_DIM + ubase + unit) * H_DIM);
#pragma unroll
        for (int c = 0; c < 8; c++) wreg[j][c] = wr[c * 32 + lane];
    }

    const unsigned tagbase = (unsigned)layer * (unsigned)(T_LEN + 1);
    float c_state = 0.f;   // meaningful for tid < 8 only

    // publish h_{-1} = 0 with tag = tagbase into the parity-1 buffers
    if (tid < UNITS) {
        unsigned long long pk = (unsigned long long)tagbase << 32;
#pragma unroll
        for (int r = 0; r < NREP; r++)
            st_relaxed64(&g_pub[1][r][ubase + tid], pk);
    }

    for (int t = 0; t < T_LEN; t++) {
        // prefetch xz for this step (independent of h; overlaps the wait)
        float xzi = 0.f, xzf = 0.f, xzg = 0.f, xzo = 0.f;
        if (tid < UNITS) {
            const float* xz = g_xz + (size_t)t * G4H + ubase + tid;
            xzi = __ldg(xz);
            xzf = __ldg(xz + H_DIM);
            xzg = __ldg(xz + 2 * H_DIM);
            xzo = __ldg(xz + 3 * H_DIM);
        }

        // wait for h_{t-1}: thread tid watches 4 fused slots of OUR replica,
        // spinning independently; once its slots are tagged it stops loading.
        {
            unsigned long long* buf = g_pub[(t + 1) & 1][rep];
            const unsigned exp_tag  = tagbase + (unsigned)t;   // tag of h_{t-1}
            unsigned long long pr0, pr1, pr2, pr3;
            int tries = 0;
            for (;;) {
                pr0 = ld_relaxed64(buf + 4 * tid + 0);
                pr1 = ld_relaxed64(buf + 4 * tid + 1);
                pr2 = ld_relaxed64(buf + 4 * tid + 2);
                pr3 = ld_relaxed64(buf + 4 * tid + 3);
                bool ok = ((unsigned)(pr0 >> 32) == exp_tag) &
                          ((unsigned)(pr1 >> 32) == exp_tag) &
                          ((unsigned)(pr2 >> 32) == exp_tag) &
                          ((unsigned)(pr3 >> 32) == exp_tag);
                if (ok) break;
                if (++tries > 2) __nanosleep(40);   // back off the hot line
            }
            // stage own h values; the single barrier below covers both
            // "all slots observed" and "smem staged".
            ((float4*)sh_h)[tid] =
                make_float4(__uint_as_float((unsigned)pr0),
                            __uint_as_float((unsigned)pr1),
                            __uint_as_float((unsigned)pr2),
                            __uint_as_float((unsigned)pr3));
        }
        __syncthreads();                                   // (B)

        // packed dot products: 4 rows per warp, 32 cols per lane (conflict-free)
        unsigned long long acc[4];
        {
            F2u z; z.f = make_float2(0.f, 0.f);
            acc[0] = acc[1] = acc[2] = acc[3] = z.u;
        }
#pragma unroll
        for (int c = 0; c < 8; c++) {
            float4 hv = ((const float4*)sh_h)[c * 32 + lane];
            F2u hlo, hhi;
            hlo.f = make_float2(hv.x, hv.y);
            hhi.f = make_float2(hv.z, hv.w);
#pragma unroll
            for (int j = 0; j < 4; j++) {
                F2u wlo, whi;
                wlo.f = make_float2(wreg[j][c].x, wreg[j][c].y);
                whi.f = make_float2(wreg[j][c].z, wreg[j][c].w);
                fma2(acc[j], wlo.u, hlo.u);
                fma2(acc[j], whi.u, hhi.u);
            }
        }

        // 4 independent butterfly reductions, interleaved so the 5-deep SHFL
        // chains pipeline across the 4 values.
        float s0, s1, s2, s3;
        {
            F2u a0, a1, a2, a3;
            a0.u = acc[0]; a1.u = acc[1]; a2.u = acc[2]; a3.u = acc[3];
            s0 = a0.f.x + a0.f.y;
            s1 = a1.f.x + a1.f.y;
            s2 = a2.f.x + a2.f.y;
            s3 = a3.f.x + a3.f.y;
#pragma unroll
            for (int off = 16; off; off >>= 1) {
                s0 += __shfl_xor_sync(0xffffffffu, s0, off);
                s1 += __shfl_xor_sync(0xffffffffu, s1, off);
                s2 += __shfl_xor_sync(0xffffffffu, s2, off);
                s3 += __shfl_xor_sync(0xffffffffu, s3, off);
            }
        }
        if (lane == 0) {
            sh_z[wid * 4 + 0] = s0;
            sh_z[wid * 4 + 1] = s1;
            sh_z[wid * 4 + 2] = s2;
            sh_z[wid * 4 + 3] = s3;
        }
        __syncthreads();                                   // (C)

        // gates on threads 0..7; sh_z[u]=i, [8+u]=f, [16+u]=g, [24+u]=o
        if (tid < UNITS) {
            float zi = sh_z[tid]      + xzi;
            float zf = sh_z[8 + tid]  + xzf;
            float zg = sh_z[16 + tid] + xzg;
            float zo = sh_z[24 + tid] + xzo;
            float ig = fast_sigmoid(zi);
            float fg = fast_sigmoid(zf);
            float gg = fast_tanh(zg);
            float og = fast_sigmoid(zo);
            c_state  = fg * c_state + ig * gg;
            float h  = og * fast_tanh(c_state);
            unsigned long long pk =
                ((unsigned long long)(tagbase + (unsigned)t + 1u) << 32) |
                (unsigned long long)__float_as_uint(h);
            unsigned long long* dst = &g_pub[t & 1][0][ubase + tid];
#pragma unroll
            for (int r = 0; r < NREP; r++)
                st_relaxed64(dst + (size_t)r * H_DIM, pk); // fused publish x4
            g_hall[(size_t)t * H_DIM + ubase + tid] = h;   // consumed next launch
        }
        // smem hazards at t+1: sh_h overwrite happens after each thread's own
        // spin; any thread reaching that point has passed (C) at t, so no
        // thread can still be reading sh_h in the t-dot (pre-(C)). sh_z
        // overwrite at t+1 is post-(B@t+1), which warp 0 reaches only after
        // gates(t). Safe with 2 barriers/step.
    }
}

// ---------------- final FC: out[t][o] = hall[t] . fcW[o] + fcb[o] ----------
__global__ void fc_kernel(const float* __restrict__ W,
                          const float* __restrict__ b,
                          float* __restrict__ out) {
    int t    = blockIdx.x;
    int o    = threadIdx.x >> 5;   // 10 warps
    int lane = threadIdx.x & 31;
    const float4* h = (const float4*)(g_hall + (size_t)t * H_DIM);
    const float4* w = (const float4*)(W + (size_t)o * H_DIM);
    float s = 0.f;
#pragma unroll
    for (int c = 0; c < 8; c++) {
        float4 hv = h[c * 32 + lane];
        float4 wv = w[c * 32 + lane];
        s += hv.x * wv.x + hv.y * wv.y + hv.z * wv.z + hv.w * wv.w;
    }
#pragma unroll
    for (int off = 16; off; off >>= 1)
        s += __shfl_xor_sync(0xffffffffu, s, off);
    if (lane == 0) out[t * 10 + o] = s + b[o];
}

// ---------------- launch ----------------------------------------------------
extern "C" void kernel_launch(void* const* d_in, const int* in_sizes, int n_in,
                              void* d_out, int out_size) {
    const float* x     = (const float*)d_in[0];
    const float* Wih0  = (const float*)d_in[1];
    const float* Whh0  = (const float*)d_in[2];
    const float* b0    = (const float*)d_in[3];
    const float* WihR  = (const float*)d_in[4];
    const float* WhhR  = (const float*)d_in[5];
    const float* bR    = (const float*)d_in[6];
    const float* fcW   = (const float*)d_in[7];
    const float* fcb   = (const float*)d_in[8];
    float*       out   = (float*)d_out;

    dim3 ggrid(G4H / 128, T_LEN / 128);
    dim3 gblk(256);

    // layer 0
    gemm_xz<IN_DIM><<<ggrid, gblk>>>(x, Wih0, b0);
    lstm_scan<<<NCTA, 256>>>(Whh0, 0);

    // layers 1..3
    for (int l = 1; l < 4; l++) {
        const float* Wih = WihR + (size_t)(l - 1) * G4H * H_DIM;
        const float* Whh = WhhR + (size_t)(l - 1) * G4H * H_DIM;
        const float* bb  = bR   + (size_t)(l - 1) * G4H;
        gemm_xz<H_DIM><<<ggrid, gblk>>>(nullptr /* = g_hall */, Wih, bb);
        lstm_scan<<<NCTA, 256>>>(Whh, l);
    }

    fc_kernel<<<T_LEN, 320>>>(fcW, fcb, out);
}

// round 14
// speedup vs baseline: 1.2383x; 1.0868x over previous
#include <cuda_runtime.h>
#include <cstdint>

#define T_LEN 4096
#define IN_DIM 256
#define H_DIM 1024
#define G4H   4096
#define NCTA  128
#define UNITS 8     // hidden units per CTA (128 * 8 = 1024)
#define NREP  4     // publish-buffer replicas (slice de-amplification)
#define GEMM_BLKS 1024   // 32x32 tile blocks for the fused K=1024 GEMM

// ---------------- device scratch (static: no allocations allowed) ----------
__device__ float g_xz[(size_t)T_LEN * G4H];     // 64 MB: input projections
__device__ float g_hall[(size_t)T_LEN * H_DIM]; // 16 MB: h outputs of current layer
// Fused data+flag publish buffers (see R8/R13 analysis; replay-safe tags).
__device__ unsigned long long g_pub[2][NREP][H_DIM];
// Per-scan-CTA progress counters: value = layer*T_LEN + t + 1, released every
// 128 steps. Zeroed by gemm0 each replay (kernel boundary orders it).
__device__ unsigned g_prog[NCTA];

// ---------------- memory-order helpers --------------------------------------
__device__ __forceinline__ unsigned long long ld_relaxed64(const unsigned long long* p) {
    unsigned long long v;
    asm volatile("ld.relaxed.gpu.global.b64 %0, [%1];" : "=l"(v) : "l"(p) : "memory");
    return v;
}
__device__ __forceinline__ void st_relaxed64(unsigned long long* p, unsigned long long v) {
    asm volatile("st.relaxed.gpu.global.b64 [%0], %1;" :: "l"(p), "l"(v) : "memory");
}
__device__ __forceinline__ unsigned ld_acquire32(const unsigned* p) {
    unsigned v;
    asm volatile("ld.acquire.gpu.global.u32 %0, [%1];" : "=r"(v) : "l"(p) : "memory");
    return v;
}
__device__ __forceinline__ void st_release32(unsigned* p, unsigned v) {
    asm volatile("st.release.gpu.global.u32 [%0], %1;" :: "l"(p), "r"(v) : "memory");
}

// ---------------- packed f32x2 FMA helpers ----------------------------------
union F2u { float2 f; unsigned long long u; };

__device__ __forceinline__ void fma2(unsigned long long& d,
                                     unsigned long long a,
                                     unsigned long long b) {
    asm volatile("fma.rn.f32x2 %0, %1, %2, %0;" : "+l"(d) : "l"(a), "l"(b));
}
__device__ __forceinline__ unsigned long long pack2(float lo, float hi) {
    unsigned long long r;
    asm("mov.b64 %0, {%1, %2};" : "=l"(r) : "f"(lo), "f"(hi));
    return r;
}

// ---------------- fast, overflow-safe activations ---------------------------
__device__ __forceinline__ float fast_sigmoid(float x) {
    return __fdividef(1.f, 1.f + __expf(-x));
}
__device__ __forceinline__ float fast_tanh(float x) {
    float a = fabsf(x);
    float e = __expf(-2.f * a);
    float t = (1.f - e) * __fdividef(1.f, 1.f + e);
    return copysignf(t, x);
}

// ---------------- standalone GEMM (layer 0 input projection) ----------------
// Also zeroes g_prog for the fused pipeline (kernel boundary orders it).
template<int K>
__global__ __launch_bounds__(256)
void gemm_xz(const float* __restrict__ A,
             const float* __restrict__ W,
             const float* __restrict__ bias) {
    __shared__ float As[16][132];
    __shared__ float Bs[16][132];

    const int tid  = threadIdx.x;
    if (blockIdx.x == 0 && blockIdx.y == 0 && tid < NCTA) g_prog[tid] = 0;

    const int row0 = blockIdx.y * 128;
    const int col0 = blockIdx.x * 128;
    const int ty   = tid >> 4;
    const int tx   = tid & 15;
    const int lr   = tid >> 2;
    const int lc   = tid & 3;

    unsigned long long acc2[8][4];
#pragma unroll
    for (int i = 0; i < 8; i++)
#pragma unroll
        for (int j = 0; j < 4; j++) acc2[i][j] = pack2(0.f, 0.f);

    const float* pA0 = A + (size_t)(row0 + lr) * K + lc * 4;
    const float* pA1 = A + (size_t)(row0 + lr + 64) * K + lc * 4;
    const float* pB0 = W + (size_t)(col0 + lr) * K + lc * 4;
    const float* pB1 = W + (size_t)(col0 + lr + 64) * K + lc * 4;

    float4 fa0 = *(const float4*)(pA0);
    float4 fa1 = *(const float4*)(pA1);
    float4 fb0 = *(const float4*)(pB0);
    float4 fb1 = *(const float4*)(pB1);

    for (int k0 = 0; k0 < K; k0 += 16) {
        __syncthreads();
        As[lc * 4 + 0][lr] = fa0.x; As[lc * 4 + 1][lr] = fa0.y;
        As[lc * 4 + 2][lr] = fa0.z; As[lc * 4 + 3][lr] = fa0.w;
        As[lc * 4 + 0][lr + 64] = fa1.x; As[lc * 4 + 1][lr + 64] = fa1.y;
        As[lc * 4 + 2][lr + 64] = fa1.z; As[lc * 4 + 3][lr + 64] = fa1.w;
        Bs[lc * 4 + 0][lr] = fb0.x; Bs[lc * 4 + 1][lr] = fb0.y;
        Bs[lc * 4 + 2][lr] = fb0.z; Bs[lc * 4 + 3][lr] = fb0.w;
        Bs[lc * 4 + 0][lr + 64] = fb1.x; Bs[lc * 4 + 1][lr + 64] = fb1.y;
        Bs[lc * 4 + 2][lr + 64] = fb1.z; Bs[lc * 4 + 3][lr + 64] = fb1.w;
        __syncthreads();

        if (k0 + 16 < K) {
            fa0 = *(const float4*)(pA0 + k0 + 16);
            fa1 = *(const float4*)(pA1 + k0 + 16);
            fb0 = *(const float4*)(pB0 + k0 + 16);
            fb1 = *(const float4*)(pB1 + k0 + 16);
        }

#pragma unroll
        for (int k = 0; k < 16; k++) {
            float4 a0 = *(const float4*)&As[k][ty * 8];
            float4 a1 = *(const float4*)&As[k][ty * 8 + 4];
            float4 b0 = *(const float4*)&Bs[k][tx * 8];
            float4 b1 = *(const float4*)&Bs[k][tx * 8 + 4];
            unsigned long long bp[4];
            bp[0] = pack2(b0.x, b0.y); bp[1] = pack2(b0.z, b0.w);
            bp[2] = pack2(b1.x, b1.y); bp[3] = pack2(b1.z, b1.w);
            float a[8] = {a0.x, a0.y, a0.z, a0.w, a1.x, a1.y, a1.z, a1.w};
#pragma unroll
            for (int i = 0; i < 8; i++) {
                unsigned long long ap = pack2(a[i], a[i]);
#pragma unroll
                for (int j = 0; j < 4; j++) fma2(acc2[i][j], ap, bp[j]);
            }
        }
    }

    float bj[8];
#pragma unroll
    for (int j = 0; j < 8; j++) bj[j] = bias[col0 + tx * 8 + j];
#pragma unroll
    for (int i = 0; i < 8; i++) {
        int r = row0 + ty * 8 + i;
        float* orow = g_xz + (size_t)r * G4H + col0 + tx * 8;
#pragma unroll
        for (int j = 0; j < 4; j++) {
            F2u v; v.u = acc2[i][j];
            orow[2 * j + 0] = v.f.x + bj[2 * j + 0];
            orow[2 * j + 1] = v.f.y + bj[2 * j + 1];
        }
    }
}

// ---------------- FUSED: scan(layer) [blocks 0..127] + gemm(layer+1) --------
// Scan path = R13 verbatim + progress release every 128 steps.
// Gemm path (blocks 128+): waits on g_prog for its 128 h-rows, then computes
// xz_{layer+1} rows. A loads via __ldcg (L2, L1-bypass: L1 not coherent with
// the concurrent scan writes).
__global__ __launch_bounds__(256, 1)
void fused_scan_gemm(const float* __restrict__ Whh, int layer,
                     const float* __restrict__ Wnext,
                     const float* __restrict__ bnext) {
    const int tid = threadIdx.x;

    if (blockIdx.x >= NCTA) {
        // ================= GEMM branch (layer+1 input projection) ==========
        __shared__ float As[16][132];
        __shared__ float Bs[16][132];

        const int g    = blockIdx.x - NCTA;
        const int row0 = (g >> 5) * 128;
        const int col0 = (g & 31) * 128;

        // wait until every scan CTA has completed step row0+127
        {
            const unsigned target = (unsigned)(layer * T_LEN + row0 + 128);
            if (tid < NCTA) {
                while (ld_acquire32(&g_prog[tid]) < target) __nanosleep(256);
            }
            __syncthreads();
        }

        const int ty = tid >> 4, tx = tid & 15;
        const int lr = tid >> 2, lc = tid & 3;

        unsigned long long acc2[8][4];
#pragma unroll
        for (int i = 0; i < 8; i++)
#pragma unroll
            for (int j = 0; j < 4; j++) acc2[i][j] = pack2(0.f, 0.f);

        const float* pA0 = g_hall + (size_t)(row0 + lr) * H_DIM + lc * 4;
        const float* pA1 = g_hall + (size_t)(row0 + lr + 64) * H_DIM + lc * 4;
        const float* pB0 = Wnext + (size_t)(col0 + lr) * H_DIM + lc * 4;
        const float* pB1 = Wnext + (size_t)(col0 + lr + 64) * H_DIM + lc * 4;

        float4 fa0 = __ldcg((const float4*)(pA0));
        float4 fa1 = __ldcg((const float4*)(pA1));
        float4 fb0 = *(const float4*)(pB0);
        float4 fb1 = *(const float4*)(pB1);

        for (int k0 = 0; k0 < H_DIM; k0 += 16) {
            __syncthreads();
            As[lc * 4 + 0][lr] = fa0.x; As[lc * 4 + 1][lr] = fa0.y;
            As[lc * 4 + 2][lr] = fa0.z; As[lc * 4 + 3][lr] = fa0.w;
            As[lc * 4 + 0][lr + 64] = fa1.x; As[lc * 4 + 1][lr + 64] = fa1.y;
            As[lc * 4 + 2][lr + 64] = fa1.z; As[lc * 4 + 3][lr + 64] = fa1.w;
            Bs[lc * 4 + 0][lr] = fb0.x; Bs[lc * 4 + 1][lr] = fb0.y;
            Bs[lc * 4 + 2][lr] = fb0.z; Bs[lc * 4 + 3][lr] = fb0.w;
            Bs[lc * 4 + 0][lr + 64] = fb1.x; Bs[lc * 4 + 1][lr + 64] = fb1.y;
            Bs[lc * 4 + 2][lr + 64] = fb1.z; Bs[lc * 4 + 3][lr + 64] = fb1.w;
            __syncthreads();

            if (k0 + 16 < H_DIM) {
                fa0 = __ldcg((const float4*)(pA0 + k0 + 16));
                fa1 = __ldcg((const float4*)(pA1 + k0 + 16));
                fb0 = *(const float4*)(pB0 + k0 + 16);
                fb1 = *(const float4*)(pB1 + k0 + 16);
            }

#pragma unroll
            for (int k = 0; k < 16; k++) {
                float4 a0 = *(const float4*)&As[k][ty * 8];
                float4 a1 = *(const float4*)&As[k][ty * 8 + 4];
                float4 b0 = *(const float4*)&Bs[k][tx * 8];
                float4 b1 = *(const float4*)&Bs[k][tx * 8 + 4];
                unsigned long long bp[4];
                bp[0] = pack2(b0.x, b0.y); bp[1] = pack2(b0.z, b0.w);
                bp[2] = pack2(b1.x, b1.y); bp[3] = pack2(b1.z, b1.w);
                float a[8] = {a0.x, a0.y, a0.z, a0.w, a1.x, a1.y, a1.z, a1.w};
#pragma unroll
                for (int i = 0; i < 8; i++) {
                    unsigned long long ap = pack2(a[i], a[i]);
#pragma unroll
                    for (int j = 0; j < 4; j++) fma2(acc2[i][j], ap, bp[j]);
                }
            }
        }

        float bj[8];
#pragma unroll
        for (int j = 0; j < 8; j++) bj[j] = bnext[col0 + tx * 8 + j];
#pragma unroll
        for (int i = 0; i < 8; i++) {
            int r = row0 + ty * 8 + i;
            float* orow = g_xz + (size_t)r * G4H + col0 + tx * 8;
#pragma unroll
            for (int j = 0; j < 4; j++) {
                F2u v; v.u = acc2[i][j];
                orow[2 * j + 0] = v.f.x + bj[2 * j + 0];
                orow[2 * j + 1] = v.f.y + bj[2 * j + 1];
            }
        }
        return;
    }

    // ==================== SCAN branch (R13 verbatim + progress) =============
    __shared__ float sh_h[H_DIM];
    __shared__ float sh_z[32];

    const int bid   = blockIdx.x;
    const int wid   = tid >> 5;
    const int lane  = tid & 31;
    const int ubase = bid * UNITS;
    const int rep   = bid & (NREP - 1);

    float4 wreg[4][8];
#pragma unroll
    for (int j = 0; j < 4; j++) {
        int s    = wid * 4 + j;
        int gate = s >> 3;
        int unit = s & 7;
        const float4* wr =
            (const float4*)(Whh + ((size_t)gate * H_DIM + ubase + unit) * H_DIM);
#pragma unroll
        for (int c = 0; c < 8; c++) wreg[j][c] = wr[c * 32 + lane];
    }

    const unsigned tagbase = (unsigned)layer * (unsigned)(T_LEN + 1);
    float c_state = 0.f;

    if (tid < UNITS) {
        unsigned long long pk = (unsigned long long)tagbase << 32;
#pragma unroll
        for (int r = 0; r < NREP; r++)
            st_relaxed64(&g_pub[1][r][ubase + tid], pk);
    }

    for (int t = 0; t < T_LEN; t++) {
        float xzi = 0.f, xzf = 0.f, xzg = 0.f, xzo = 0.f;
        if (tid < UNITS) {
            const float* xz = g_xz + (size_t)t * G4H + ubase + tid;
            xzi = __ldg(xz);
            xzf = __ldg(xz + H_DIM);
            xzg = __ldg(xz + 2 * H_DIM);
            xzo = __ldg(xz + 3 * H_DIM);
        }

        {
            unsigned long long* buf = g_pub[(t + 1) & 1][rep];
            const unsigned exp_tag  = tagbase + (unsigned)t;
            unsigned long long pr0, pr1, pr2, pr3;
            int tries = 0;
            for (;;) {
                pr0 = ld_relaxed64(buf + 4 * tid + 0);
                pr1 = ld_relaxed64(buf + 4 * tid + 1);
                pr2 = ld_relaxed64(buf + 4 * tid + 2);
                pr3 = ld_relaxed64(buf + 4 * tid + 3);
                bool ok = ((unsigned)(pr0 >> 32) == exp_tag) &
                          ((unsigned)(pr1 >> 32) == exp_tag) &
                          ((unsigned)(pr2 >> 32) == exp_tag) &
                          ((unsigned)(pr3 >> 32) == exp_tag);
                if (ok) break;
                if (++tries > 2) __nanosleep(40);
            }
            ((float4*)sh_h)[tid] =
                make_float4(__uint_as_float((unsigned)pr0),
                            __uint_as_float((unsigned)pr1),
                            __uint_as_float((unsigned)pr2),
                            __uint_as_float((unsigned)pr3));
        }
        __syncthreads();                                   // (B)

        unsigned long long acc[4];
        {
            F2u z; z.f = make_float2(0.f, 0.f);
            acc[0] = acc[1] = acc[2] = acc[3] = z.u;
        }
#pragma unroll
        for (int c = 0; c < 8; c++) {
            float4 hv = ((const float4*)sh_h)[c * 32 + lane];
            F2u hlo, hhi;
            hlo.f = make_float2(hv.x, hv.y);
            hhi.f = make_float2(hv.z, hv.w);
#pragma unroll
            for (int j = 0; j < 4; j++) {
                F2u wlo, whi;
                wlo.f = make_float2(wreg[j][c].x, wreg[j][c].y);
                whi.f = make_float2(wreg[j][c].z, wreg[j][c].w);
                fma2(acc[j], wlo.u, hlo.u);
                fma2(acc[j], whi.u, hhi.u);
            }
        }

        float s0, s1, s2, s3;
        {
            F2u a0, a1, a2, a3;
            a0.u = acc[0]; a1.u = acc[1]; a2.u = acc[2]; a3.u = acc[3];
            s0 = a0.f.x + a0.f.y;
            s1 = a1.f.x + a1.f.y;
            s2 = a2.f.x + a2.f.y;
            s3 = a3.f.x + a3.f.y;
#pragma unroll
            for (int off = 16; off; off >>= 1) {
                s0 += __shfl_xor_sync(0xffffffffu, s0, off);
                s1 += __shfl_xor_sync(0xffffffffu, s1, off);
                s2 += __shfl_xor_sync(0xffffffffu, s2, off);
                s3 += __shfl_xor_sync(0xffffffffu, s3, off);
            }
        }
        if (lane == 0) {
            sh_z[wid * 4 + 0] = s0;
            sh_z[wid * 4 + 1] = s1;
            sh_z[wid * 4 + 2] = s2;
            sh_z[wid * 4 + 3] = s3;
        }
        __syncthreads();                                   // (C)

        if (tid < UNITS) {
            float zi = sh_z[tid]      + xzi;
            float zf = sh_z[8 + tid]  + xzf;
            float zg = sh_z[16 + tid] + xzg;
            float zo = sh_z[24 + tid] + xzo;
            float ig = fast_sigmoid(zi);
            float fg = fast_sigmoid(zf);
            float gg = fast_tanh(zg);
            float og = fast_sigmoid(zo);
            c_state  = fg * c_state + ig * gg;
            float h  = og * fast_tanh(c_state);
            unsigned long long pk =
                ((unsigned long long)(tagbase + (unsigned)t + 1u) << 32) |
                (unsigned long long)__float_as_uint(h);
            unsigned long long* dst = &g_pub[t & 1][0][ubase + tid];
#pragma unroll
            for (int r = 0; r < NREP; r++)
                st_relaxed64(dst + (size_t)r * H_DIM, pk);
            g_hall[(size_t)t * H_DIM + ubase + tid] = h;

            // progress release every 128 steps: syncwarp(0xff) orders lanes
            // 0..7's g_hall stores before lane 0's release.
            if ((t & 127) == 127) {
                __syncwarp(0x000000ffu);
                if (tid == 0)
                    st_release32(&g_prog[bid],
                                 (unsigned)(layer * T_LEN) + (unsigned)t + 1u);
            }
        }
    }
}

// ---------------- final FC: out[t][o] = hall[t] . fcW[o] + fcb[o] ----------
__global__ void fc_kernel(const float* __restrict__ W,
                          const float* __restrict__ b,
                          float* __restrict__ out) {
    int t    = blockIdx.x;
    int o    = threadIdx.x >> 5;   // 10 warps
    int lane = threadIdx.x & 31;
    const float4* h = (const float4*)(g_hall + (size_t)t * H_DIM);
    const float4* w = (const float4*)(W + (size_t)o * H_DIM);
    float s = 0.f;
#pragma unroll
    for (int c = 0; c < 8; c++) {
        float4 hv = h[c * 32 + lane];
        float4 wv = w[c * 32 + lane];
        s += hv.x * wv.x + hv.y * wv.y + hv.z * wv.z + hv.w * wv.w;
    }
#pragma unroll
    for (int off = 16; off; off >>= 1)
        s += __shfl_xor_sync(0xffffffffu, s, off);
    if (lane == 0) out[t * 10 + o] = s + b[o];
}

// ---------------- launch ----------------------------------------------------
extern "C" void kernel_launch(void* const* d_in, const int* in_sizes, int n_in,
                              void* d_out, int out_size) {
    const float* x     = (const float*)d_in[0];
    const float* Wih0  = (const float*)d_in[1];
    const float* Whh0  = (const float*)d_in[2];
    const float* b0    = (const float*)d_in[3];
    const float* WihR  = (const float*)d_in[4];
    const float* WhhR  = (const float*)d_in[5];
    const float* bR    = (const float*)d_in[6];
    const float* fcW   = (const float*)d_in[7];
    const float* fcb   = (const float*)d_in[8];
    float*       out   = (float*)d_out;

    const size_t wstride = (size_t)G4H * H_DIM;

    // layer-0 input projection (also zeroes g_prog for this replay)
    dim3 ggrid(G4H / 128, T_LEN / 128);
    gemm_xz<IN_DIM><<<ggrid, 256>>>(x, Wih0, b0);

    // K_l = scan(l) + gemm(l+1), l = 0..2
    fused_scan_gemm<<<NCTA + GEMM_BLKS, 256>>>(Whh0, 0, WihR, bR);
    fused_scan_gemm<<<NCTA + GEMM_BLKS, 256>>>(WhhR, 1, WihR + wstride, bR + G4H);
    fused_scan_gemm<<<NCTA + GEMM_BLKS, 256>>>(WhhR + wstride, 2,
                                               WihR + 2 * wstride, bR + 2 * G4H);
    // K_3 = scan(3) only
    fused_scan_gemm<<<NCTA, 256>>>(WhhR + 2 * wstride, 3, nullptr, nullptr);

    fc_kernel<<<T_LEN, 320>>>(fcW, fcb, out);
}